// round 1
// baseline (speedup 1.0000x reference)
#include <cuda_runtime.h>

// GCNRFPEncode: out = BN( 0.5*invsq[s]*sum_{e:src=s} invsq[dst]*h[dst] + 0.5*deg[s]*h[s] )
// with h = X@W + b, deg = #edges per src, invsq = deg^-1/2.
// Factored: g[v] = invsq[v]*h[v];  self term = 0.5*deg^1.5*g[s].

#define FF 128
#define HH 64
#define NMAX 100000
#define BN_EPS 0.001f

// Scratch (device globals; no allocations allowed)
__device__ float g_deg[NMAX];
__device__ float g_g[(size_t)NMAX * HH];
__device__ float g_WT[HH * FF];

// ---------------- init: zero deg + zero d_out (accumulator for S) --------------
__global__ void k_init(float4* __restrict__ out4, int n4, int N) {
    int t = blockIdx.x * blockDim.x + threadIdx.x;
    if (t < n4) out4[t] = make_float4(0.f, 0.f, 0.f, 0.f);
    if (t < N) g_deg[t] = 0.f;
}

// ---------------- transpose W [F,H] -> WT [H,F] --------------------------------
__global__ void k_wt(const float* __restrict__ W) {
    int t = blockIdx.x * blockDim.x + threadIdx.x;
    if (t < FF * HH) {
        int k = t / HH, j = t % HH;
        g_WT[j * FF + k] = W[t];
    }
}

// ---------------- degree count --------------------------------------------------
__global__ void k_deg(const int2* __restrict__ edge, int E) {
    int t = blockIdx.x * blockDim.x + threadIdx.x;
    if (t < E) {
        int2 sd = edge[t];
        atomicAdd(&g_deg[sd.x], 1.0f);   // compiles to RED (no return)
    }
}

// ---------------- GEMM: g = (X@W + b) * rsqrt(deg) ------------------------------
// block: 32 rows x 64 cols, 256 threads, each thread 4 rows x 2 cols.
__global__ __launch_bounds__(256) void k_gemm(const float* __restrict__ X,
                                              const float* __restrict__ b,
                                              int N) {
    __shared__ float4 sWT[HH][FF / 4];   // 32 KB
    __shared__ float4 sX[32][FF / 4];    // 16 KB
    int tid = threadIdx.x;
    int row0 = blockIdx.x * 32;
    int rows = N - row0; if (rows > 32) rows = 32;

    for (int i = tid; i < HH * FF / 4; i += 256)
        ((float4*)sWT)[i] = ((const float4*)g_WT)[i];
    for (int i = tid; i < rows * (FF / 4); i += 256)
        ((float4*)sX)[i] = ((const float4*)(X + (size_t)row0 * FF))[i];
    __syncthreads();

    int j0 = tid & 31;       // cols j0, j0+32
    int rg = tid >> 5;       // row group 0..7 -> rows rg*4 .. rg*4+3

    float acc[4][2];
    float b0 = b[j0], b1 = b[j0 + 32];
#pragma unroll
    for (int r = 0; r < 4; r++) { acc[r][0] = b0; acc[r][1] = b1; }

#pragma unroll
    for (int k4 = 0; k4 < FF / 4; k4++) {
        float4 w0 = sWT[j0][k4];
        float4 w1 = sWT[j0 + 32][k4];
#pragma unroll
        for (int r = 0; r < 4; r++) {
            float4 x = sX[rg * 4 + r][k4];
            acc[r][0] += x.x * w0.x + x.y * w0.y + x.z * w0.z + x.w * w0.w;
            acc[r][1] += x.x * w1.x + x.y * w1.y + x.z * w1.z + x.w * w1.w;
        }
    }

#pragma unroll
    for (int r = 0; r < 4; r++) {
        int row = row0 + rg * 4 + r;
        if (row < N) {
            float is = rsqrtf(g_deg[row]);
            g_g[(size_t)row * HH + j0]      = acc[r][0] * is;
            g_g[(size_t)row * HH + j0 + 32] = acc[r][1] * is;
        }
    }
}

// ---------------- edge aggregation: S[src] += g[dst]  (into d_out) ---------------
// 16 threads per edge, one float4 gather + one red.global.add.v4.f32 each.
__global__ void k_edge(const int2* __restrict__ edge,
                       float* __restrict__ S, int E) {
    int t = blockIdx.x * blockDim.x + threadIdx.x;
    int e = t >> 4, q = t & 15;
    if (e >= E) return;
    int2 sd = edge[e];
    float4 v = __ldg(((const float4*)(g_g + (size_t)sd.y * HH)) + q);
    float* p = S + (size_t)sd.x * HH + (q << 2);
    asm volatile("red.global.add.v4.f32 [%0], {%1,%2,%3,%4};"
                 :: "l"(p), "f"(v.x), "f"(v.y), "f"(v.z), "f"(v.w)
                 : "memory");
}

// ---------------- finalize: out = BN(0.5*invsq*S + 0.5*deg^1.5*g) ---------------
__global__ void k_final(float* __restrict__ out,
                        const float* __restrict__ gamma,
                        const float* __restrict__ beta,
                        const float* __restrict__ mean,
                        const float* __restrict__ var,
                        int N) {
    int t = blockIdx.x * blockDim.x + threadIdx.x;
    int v = t >> 4, q = t & 15;
    if (v >= N) return;
    float d  = g_deg[v];
    float hs = 0.5f * rsqrtf(d);          // 0.5 * invsq
    float sc = 0.5f * d * sqrtf(d);       // 0.5 * deg^1.5
    float4 S4 = ((const float4*)out)[t];
    float4 g4 = ((const float4*)g_g)[t];
    int j = q << 2;
    float o[4];
    float sv[4] = {S4.x, S4.y, S4.z, S4.w};
    float gv[4] = {g4.x, g4.y, g4.z, g4.w};
#pragma unroll
    for (int c = 0; c < 4; c++) {
        float a = hs * sv[c] + sc * gv[c];
        float scale = gamma[j + c] * rsqrtf(var[j + c] + BN_EPS);
        o[c] = (a - mean[j + c]) * scale + beta[j + c];
    }
    ((float4*)out)[t] = make_float4(o[0], o[1], o[2], o[3]);
}

// ---------------- launch ---------------------------------------------------------
extern "C" void kernel_launch(void* const* d_in, const int* in_sizes, int n_in,
                              void* d_out, int out_size) {
    const float* X     = (const float*)d_in[0];
    const float* W     = (const float*)d_in[1];
    const float* b     = (const float*)d_in[2];
    const float* gamma = (const float*)d_in[3];
    const float* beta  = (const float*)d_in[4];
    const float* mean  = (const float*)d_in[5];
    const float* var   = (const float*)d_in[6];
    const int2*  edge  = (const int2*)d_in[7];

    int N = in_sizes[0] / FF;
    int E = in_sizes[7] / 2;
    float* out = (float*)d_out;

    int n4 = N * HH / 4;
    k_init<<<(n4 + 255) / 256, 256>>>((float4*)out, n4, N);
    k_wt<<<(FF * HH + 255) / 256, 256>>>(W);
    k_deg<<<(E + 255) / 256, 256>>>(edge, E);
    k_gemm<<<(N + 31) / 32, 256>>>(X, b, N);
    {
        long long tot = (long long)E * 16;
        k_edge<<<(int)((tot + 255) / 256), 256>>>(edge, out, E);
    }
    k_final<<<(N * 16 + 255) / 256, 256>>>(out, gamma, beta, mean, var, N);
}

// round 2
// speedup vs baseline: 2.1599x; 2.1599x over previous
#include <cuda_runtime.h>

// GCNRFPEncode: out = BN( 0.5*invsq[s]*sum_{e:src=s} invsq[dst]*h[dst] + 0.5*deg[s]^1.5*g[s] )
// with h = X@W + b, g[v] = invsq(deg[v]) * h[v].

#define FF 128
#define HH 64
#define NMAX 100000
#define BN_EPS 0.001f

__device__ float g_deg[NMAX];
__device__ float g_g[(size_t)NMAX * HH];

// ---------------- packed f32x2 helpers ------------------------------------------
__device__ __forceinline__ unsigned long long ffma2(unsigned long long a,
                                                    unsigned long long b,
                                                    unsigned long long c) {
    unsigned long long d;
    asm("fma.rn.f32x2 %0, %1, %2, %3;" : "=l"(d) : "l"(a), "l"(b), "l"(c));
    return d;
}
__device__ __forceinline__ float2 unpack2(unsigned long long v) {
    float2 r;
    asm("mov.b64 {%0, %1}, %2;" : "=f"(r.x), "=f"(r.y) : "l"(v));
    return r;
}

// ---------------- init: zero deg + zero d_out (accumulator for S) ---------------
__global__ void k_init(float4* __restrict__ out4, int n4, int N) {
    int t = blockIdx.x * blockDim.x + threadIdx.x;
    if (t < n4) out4[t] = make_float4(0.f, 0.f, 0.f, 0.f);
    if (t < N) g_deg[t] = 0.f;
}

// ---------------- degree count ---------------------------------------------------
__global__ void k_deg(const int2* __restrict__ edge, int E) {
    int t = blockIdx.x * blockDim.x + threadIdx.x;
    if (t < E) {
        int2 sd = edge[t];
        atomicAdd(&g_deg[sd.x], 1.0f);   // RED
    }
}

// ---------------- GEMM: g = (X@W + b) * rsqrt(deg) -------------------------------
// Block tile: 128 rows x 64 cols (full H), 256 threads, thread tile 8 rows x 4 cols.
// Packed-k FFMA2: acc holds even/odd-k partial sums; no packing movs needed.
// smem: sX [128 rows][32 k4] float4 (row-major, warp-broadcast reads)
//       sW [32 k4][64 col] float4 where element = {W[4k4+0..3][col]} (lane-consecutive reads)
extern __shared__ unsigned long long g_smem[];

__global__ __launch_bounds__(256, 2) void k_gemm(const float* __restrict__ X,
                                                 const float* __restrict__ W,
                                                 const float* __restrict__ b,
                                                 int N) {
    ulonglong2* sX = (ulonglong2*)g_smem;            // 128*32 ull2 = 64 KB
    ulonglong2* sW = sX + 128 * 32;                  // 32*64  ull2 = 32 KB
    float4* sX4 = (float4*)sX;
    float4* sW4 = (float4*)sW;

    int tid = threadIdx.x;
    int row0 = blockIdx.x * 128;
    int maxr = N - row0;                             // valid rows in this block

    // Stage X tile (coalesced, zero-fill OOB)
    const float4* Xg = (const float4*)X + (size_t)row0 * 32;
#pragma unroll
    for (int it = 0; it < 16; it++) {
        int i = tid + it * 256;
        int r = i >> 5;
        float4 v = make_float4(0.f, 0.f, 0.f, 0.f);
        if (r < maxr) v = Xg[i];
        sX4[i] = v;
    }
    // Stage W as k-packed columns
#pragma unroll
    for (int it = 0; it < 8; it++) {
        int j = tid + it * 256;
        int col = j & 63, k4 = j >> 6;
        float4 w;
        w.x = W[(4 * k4 + 0) * HH + col];
        w.y = W[(4 * k4 + 1) * HH + col];
        w.z = W[(4 * k4 + 2) * HH + col];
        w.w = W[(4 * k4 + 3) * HH + col];
        sW4[j] = w;
    }
    __syncthreads();

    int tx = tid & 15;           // col base: cols tx + 16c
    int ty = tid >> 4;           // row group: rows ty*8 .. ty*8+7
    int r0 = ty * 8;

    float bv[4];
#pragma unroll
    for (int c = 0; c < 4; c++) bv[c] = b[tx + 16 * c];

    unsigned long long acc[8][4];
#pragma unroll
    for (int r = 0; r < 8; r++)
#pragma unroll
        for (int c = 0; c < 4; c++) acc[r][c] = 0ull;

#pragma unroll 2
    for (int k4 = 0; k4 < 32; k4++) {
        ulonglong2 w0 = sW[k4 * 64 + tx];
        ulonglong2 w1 = sW[k4 * 64 + tx + 16];
        ulonglong2 w2 = sW[k4 * 64 + tx + 32];
        ulonglong2 w3 = sW[k4 * 64 + tx + 48];
#pragma unroll
        for (int r = 0; r < 8; r++) {
            ulonglong2 x = sX[(r0 + r) * 32 + k4];
            acc[r][0] = ffma2(x.x, w0.x, acc[r][0]);
            acc[r][1] = ffma2(x.x, w1.x, acc[r][1]);
            acc[r][2] = ffma2(x.x, w2.x, acc[r][2]);
            acc[r][3] = ffma2(x.x, w3.x, acc[r][3]);
            acc[r][0] = ffma2(x.y, w0.y, acc[r][0]);
            acc[r][1] = ffma2(x.y, w1.y, acc[r][1]);
            acc[r][2] = ffma2(x.y, w2.y, acc[r][2]);
            acc[r][3] = ffma2(x.y, w3.y, acc[r][3]);
        }
    }

#pragma unroll
    for (int r = 0; r < 8; r++) {
        int row = row0 + r0 + r;
        if (row < N) {
            float is = rsqrtf(g_deg[row]);
            float* gp = g_g + (size_t)row * HH;
#pragma unroll
            for (int c = 0; c < 4; c++) {
                float2 p = unpack2(acc[r][c]);
                gp[tx + 16 * c] = (p.x + p.y + bv[c]) * is;
            }
        }
    }
}

// ---------------- edge aggregation: S[src] += g[dst] (into d_out) ----------------
__global__ void k_edge(const int2* __restrict__ edge,
                       float* __restrict__ S, int E) {
    int t = blockIdx.x * blockDim.x + threadIdx.x;
    int e = t >> 4, q = t & 15;
    if (e >= E) return;
    int2 sd = edge[e];
    float4 v = __ldg(((const float4*)(g_g + (size_t)sd.y * HH)) + q);
    float* p = S + (size_t)sd.x * HH + (q << 2);
    asm volatile("red.global.add.v4.f32 [%0], {%1,%2,%3,%4};"
                 :: "l"(p), "f"(v.x), "f"(v.y), "f"(v.z), "f"(v.w)
                 : "memory");
}

// ---------------- finalize: out = BN(0.5*invsq*S + 0.5*deg^1.5*g) ----------------
__global__ void k_final(float* __restrict__ out,
                        const float* __restrict__ gamma,
                        const float* __restrict__ beta,
                        const float* __restrict__ mean,
                        const float* __restrict__ var,
                        int N) {
    int t = blockIdx.x * blockDim.x + threadIdx.x;
    int v = t >> 4, q = t & 15;
    if (v >= N) return;
    float d  = g_deg[v];
    float hs = 0.5f * rsqrtf(d);          // 0.5 * deg^-1/2
    float sc = 0.5f * d * sqrtf(d);       // 0.5 * deg^1.5
    float4 S4 = ((const float4*)out)[t];
    float4 g4 = ((const float4*)g_g)[t];
    int j = q << 2;
    float sv[4] = {S4.x, S4.y, S4.z, S4.w};
    float gv[4] = {g4.x, g4.y, g4.z, g4.w};
    float o[4];
#pragma unroll
    for (int c = 0; c < 4; c++) {
        float a = hs * sv[c] + sc * gv[c];
        float scale = gamma[j + c] * rsqrtf(var[j + c] + BN_EPS);
        o[c] = (a - mean[j + c]) * scale + beta[j + c];
    }
    ((float4*)out)[t] = make_float4(o[0], o[1], o[2], o[3]);
}

// ---------------- launch ----------------------------------------------------------
extern "C" void kernel_launch(void* const* d_in, const int* in_sizes, int n_in,
                              void* d_out, int out_size) {
    const float* X     = (const float*)d_in[0];
    const float* W     = (const float*)d_in[1];
    const float* b     = (const float*)d_in[2];
    const float* gamma = (const float*)d_in[3];
    const float* beta  = (const float*)d_in[4];
    const float* mean  = (const float*)d_in[5];
    const float* var   = (const float*)d_in[6];
    const int2*  edge  = (const int2*)d_in[7];

    int N = in_sizes[0] / FF;
    int E = in_sizes[7] / 2;
    float* out = (float*)d_out;

    static const int SMEM = 96 * 1024;
    cudaFuncSetAttribute(k_gemm, cudaFuncAttributeMaxDynamicSharedMemorySize, SMEM);

    int n4 = N * HH / 4;
    k_init<<<(n4 + 255) / 256, 256>>>((float4*)out, n4, N);
    k_deg<<<(E + 255) / 256, 256>>>(edge, E);
    k_gemm<<<(N + 127) / 128, 256, SMEM>>>(X, W, b, N);
    {
        long long tot = (long long)E * 16;
        k_edge<<<(int)((tot + 255) / 256), 256>>>(edge, out, E);
    }
    k_final<<<(N * 16 + 255) / 256, 256>>>(out, gamma, beta, mean, var, N);
}